// round 13
// baseline (speedup 1.0000x reference)
#include <cuda_runtime.h>
#include <math.h>

// NeuralODE on GB300, round 13 — consolidation of measured bests.
// ode_kernel: R3 architecture + MUFU.TANH (validated: rel_err 2.3e-6) +
//   precomputed dt*coef combo registers (one fewer instr + 4 cyc less serial
//   latency per combo value).
// dec_kernel: exact R11 cp.async depth-2 pipeline (measured 92.1us,
//   better than R12's depth-3 96.5us).

namespace {

constexpr int kB = 4096;
constexpr int kT = 101;
constexpr int kH = 64;
constexpr int NSTEPS = kT - 1;

constexpr int NB = 2;
constexpr int WARPS = 4;
constexpr int THREADS = WARPS * 32;
constexpr int ELEMS_PER_BLOCK = WARPS * NB;  // 8
constexpr int GRID = kB / ELEMS_PER_BLOCK;   // 512

constexpr float A21 = 0.161f;
constexpr float A31 = -0.008480655492356989f, A32 = 0.335480655492357f;
constexpr float A41 = 2.8971530571054935f, A42 = -6.359448489975075f, A43 = 4.3622954328695815f;
constexpr float A51 = 5.325864828439257f, A52 = -11.748883564062828f;
constexpr float A53 = 7.4955393428898365f, A54 = -0.09249506636175525f;
constexpr float A61 = 5.86145544294642f, A62 = -12.92096931784711f;
constexpr float A63 = 8.159367898576159f, A64 = -0.071584973281401f, A65 = -0.028269050394068383f;
constexpr float B1c = 0.09646076681806523f, B2c = 0.01f, B3c = 0.4798896504144996f;
constexpr float B4c = 1.379008574103742f, B5c = -3.290069515436081f, B6c = 2.324710524099774f;

using u64 = unsigned long long;

__device__ __forceinline__ u64 pk(float x, float y) {
    u64 r; asm("mov.b64 %0, {%1,%2};" : "=l"(r) : "f"(x), "f"(y)); return r;
}
__device__ __forceinline__ u64 fma2(u64 a, u64 b, u64 c) {
    u64 d; asm("fma.rn.f32x2 %0, %1, %2, %3;" : "=l"(d) : "l"(a), "l"(b), "l"(c)); return d;
}
__device__ __forceinline__ float hsum2(u64 a, u64 b) {
    u64 s; asm("add.rn.f32x2 %0, %1, %2;" : "=l"(s) : "l"(a), "l"(b));
    float x, y;
    asm("mov.b64 {%0,%1}, %2;" : "=f"(x), "=f"(y) : "l"(s));
    return x + y;
}
__device__ __forceinline__ float tanh_f(float x) {
    // MUFU.TANH (validated round 12: rel_err 2.3e-6 vs 1e-3 gate)
    float r; asm("tanh.approx.f32 %0, %1;" : "=f"(r) : "f"(x));
    return r;
}
__device__ __forceinline__ unsigned smem_u32(const void* p) {
    unsigned a;
    asm("{ .reg .u64 t; cvta.to.shared.u64 t, %1; cvt.u32.u64 %0, t; }"
        : "=r"(a) : "l"(p));
    return a;
}
__device__ __forceinline__ void cp_async16(unsigned saddr, const void* gptr) {
    asm volatile("cp.async.cg.shared.global [%0], [%1], 16;"
                 :: "r"(saddr), "l"(gptr) : "memory");
}

__global__ void __launch_bounds__(THREADS, 2)
ode_kernel(
    const float* __restrict__ ts, const float* __restrict__ y0,
    const float* __restrict__ encW, const float* __restrict__ encb,
    const float* __restrict__ W1g, const float* __restrict__ b1g,
    const float* __restrict__ W2g, const float* __restrict__ b2g,
    const float* __restrict__ W3g, const float* __restrict__ b3g,
    float* __restrict__ zs)
{
    // per warp: suA[64] suB[64] sh1A[32] sh1B[32] sh2A[32] sh2B[32]
    __shared__ __align__(16) float sm[WARPS * 256];
    const int lane = threadIdx.x & 31;
    const int wid = threadIdx.x >> 5;
    float* suA  = sm + wid * 256;
    float* suB  = suA + 64;
    float* sh1A = suA + 128;
    float* sh1B = suA + 160;
    float* sh2A = suA + 192;
    float* sh2B = suA + 224;
    const int bA = blockIdx.x * ELEMS_PER_BLOCK + wid * NB;
    const int bB = bA + 1;

    // ---- register-resident MLP weights, K-packed ----
    u64 w1p[32];   // W1[lane][0..63]
    u64 w2p[16];   // W2[lane][0..31]
    u64 w3a[16];   // W3[2*lane][0..31]
    u64 w3b[16];   // W3[2*lane+1][0..31]
    {
        const ulonglong2* v1 = reinterpret_cast<const ulonglong2*>(W1g + lane * 64);
#pragma unroll
        for (int i = 0; i < 16; i++) { ulonglong2 v = v1[i]; w1p[2*i] = v.x; w1p[2*i+1] = v.y; }
        const ulonglong2* v2 = reinterpret_cast<const ulonglong2*>(W2g + lane * 32);
#pragma unroll
        for (int i = 0; i < 8; i++) { ulonglong2 v = v2[i]; w2p[2*i] = v.x; w2p[2*i+1] = v.y; }
        const ulonglong2* v3a = reinterpret_cast<const ulonglong2*>(W3g + (2*lane) * 32);
        const ulonglong2* v3b = reinterpret_cast<const ulonglong2*>(W3g + (2*lane+1) * 32);
#pragma unroll
        for (int i = 0; i < 8; i++) {
            ulonglong2 a = v3a[i], b = v3b[i];
            w3a[2*i] = a.x; w3a[2*i+1] = a.y;
            w3b[2*i] = b.x; w3b[2*i+1] = b.y;
        }
    }
    const float b1r = b1g[lane];
    const float b2r = b2g[lane];
    const float2 b3p = *reinterpret_cast<const float2*>(b3g + 2 * lane);
    const float dt = (ts[kT - 1] - ts[0]) / (float)NSTEPS;

    // precomputed dt*coef (identical products to reference's dt*(sum coef*k))
    const float dA21 = dt * A21;
    const float dA31 = dt * A31, dA32 = dt * A32;
    const float dA41 = dt * A41, dA42 = dt * A42, dA43 = dt * A43;
    const float dA51 = dt * A51, dA52 = dt * A52, dA53 = dt * A53, dA54 = dt * A54;
    const float dA61 = dt * A61, dA62 = dt * A62, dA63 = dt * A63, dA64 = dt * A64, dA65 = dt * A65;
    const float dB1 = dt * B1c, dB2 = dt * B2c, dB3 = dt * B3c;
    const float dB4 = dt * B4c, dB5 = dt * B5c, dB6 = dt * B6c;

    // ---- encoder for both elements ----
    float zA0, zA1, zB0, zB1;
    {
        reinterpret_cast<float2*>(suA)[lane] =
            *reinterpret_cast<const float2*>(y0 + (size_t)bA * 64 + 2 * lane);
        reinterpret_cast<float2*>(suB)[lane] =
            *reinterpret_cast<const float2*>(y0 + (size_t)bB * 64 + 2 * lane);
        __syncwarp();
        const ulonglong2* Ea = reinterpret_cast<const ulonglong2*>(encW + (2*lane) * 64);
        const ulonglong2* Eb = reinterpret_cast<const ulonglong2*>(encW + (2*lane+1) * 64);
        const float2 eb = *reinterpret_cast<const float2*>(encb + 2 * lane);
        u64 aA0 = pk(eb.x, 0.f), aA1 = 0, cA0 = pk(eb.y, 0.f), cA1 = 0;
        u64 aB0 = pk(eb.x, 0.f), aB1 = 0, cB0 = pk(eb.y, 0.f), cB1 = 0;
        const ulonglong2* uA = reinterpret_cast<const ulonglong2*>(suA);
        const ulonglong2* uB = reinterpret_cast<const ulonglong2*>(suB);
#pragma unroll
        for (int kc = 0; kc < 16; kc++) {
            ulonglong2 wA = Ea[kc], wB = Eb[kc];
            ulonglong2 vA = uA[kc], vB = uB[kc];
            aA0 = fma2(vA.x, wA.x, aA0); aA1 = fma2(vA.y, wA.y, aA1);
            cA0 = fma2(vA.x, wB.x, cA0); cA1 = fma2(vA.y, wB.y, cA1);
            aB0 = fma2(vB.x, wA.x, aB0); aB1 = fma2(vB.y, wA.y, aB1);
            cB0 = fma2(vB.x, wB.x, cB0); cB1 = fma2(vB.y, wB.y, cB1);
        }
        zA0 = hsum2(aA0, aA1); zA1 = hsum2(cA0, cA1);
        zB0 = hsum2(aB0, aB1); zB1 = hsum2(cB0, cB1);
        __syncwarp();
    }

    // MLP field eval for both elements; input in suA/suB.
    auto mlp2 = [&](float& oAl, float& oAh, float& oBl, float& oBh) {
        // layer 1: 64 -> 32, tanh
        u64 aA0 = pk(b1r, 0.f), aA1 = 0, aB0 = pk(b1r, 0.f), aB1 = 0;
        {
            const ulonglong2* uA = reinterpret_cast<const ulonglong2*>(suA);
            const ulonglong2* uB = reinterpret_cast<const ulonglong2*>(suB);
#pragma unroll
            for (int kc = 0; kc < 16; kc++) {
                ulonglong2 vA = uA[kc], vB = uB[kc];
                aA0 = fma2(vA.x, w1p[2*kc], aA0); aA1 = fma2(vA.y, w1p[2*kc+1], aA1);
                aB0 = fma2(vB.x, w1p[2*kc], aB0); aB1 = fma2(vB.y, w1p[2*kc+1], aB1);
            }
        }
        sh1A[lane] = tanh_f(hsum2(aA0, aA1));
        sh1B[lane] = tanh_f(hsum2(aB0, aB1));
        __syncwarp();
        // layer 2: 32 -> 32, tanh
        u64 cA0 = pk(b2r, 0.f), cA1 = 0, cB0 = pk(b2r, 0.f), cB1 = 0;
        {
            const ulonglong2* hA = reinterpret_cast<const ulonglong2*>(sh1A);
            const ulonglong2* hB = reinterpret_cast<const ulonglong2*>(sh1B);
#pragma unroll
            for (int kc = 0; kc < 8; kc++) {
                ulonglong2 vA = hA[kc], vB = hB[kc];
                cA0 = fma2(vA.x, w2p[2*kc], cA0); cA1 = fma2(vA.y, w2p[2*kc+1], cA1);
                cB0 = fma2(vB.x, w2p[2*kc], cB0); cB1 = fma2(vB.y, w2p[2*kc+1], cB1);
            }
        }
        sh2A[lane] = tanh_f(hsum2(cA0, cA1));
        sh2B[lane] = tanh_f(hsum2(cB0, cB1));
        __syncwarp();
        // layer 3: 32 -> 64 (lane outputs comps 2*lane, 2*lane+1)
        u64 dA0 = pk(b3p.x, 0.f), dA1 = 0, eA0 = pk(b3p.y, 0.f), eA1 = 0;
        u64 dB0 = pk(b3p.x, 0.f), dB1 = 0, eB0 = pk(b3p.y, 0.f), eB1 = 0;
        {
            const ulonglong2* hA = reinterpret_cast<const ulonglong2*>(sh2A);
            const ulonglong2* hB = reinterpret_cast<const ulonglong2*>(sh2B);
#pragma unroll
            for (int kc = 0; kc < 8; kc++) {
                ulonglong2 vA = hA[kc], vB = hB[kc];
                dA0 = fma2(vA.x, w3a[2*kc], dA0); dA1 = fma2(vA.y, w3a[2*kc+1], dA1);
                eA0 = fma2(vA.x, w3b[2*kc], eA0); eA1 = fma2(vA.y, w3b[2*kc+1], eA1);
                dB0 = fma2(vB.x, w3a[2*kc], dB0); dB1 = fma2(vB.y, w3a[2*kc+1], dB1);
                eB0 = fma2(vB.x, w3b[2*kc], eB0); eB1 = fma2(vB.y, w3b[2*kc+1], eB1);
            }
        }
        oAl = hsum2(dA0, dA1); oAh = hsum2(eA0, eA1);
        oBl = hsum2(dB0, dB1); oBh = hsum2(eB0, eB1);
    };

    auto setu2 = [&](float uAl, float uAh, float uBl, float uBh) {
        reinterpret_cast<float2*>(suA)[lane] = make_float2(uAl, uAh);
        reinterpret_cast<float2*>(suB)[lane] = make_float2(uBl, uBh);
        __syncwarp();
    };

    float k1Al, k1Ah, k2Al, k2Ah, k3Al, k3Ah, k4Al, k4Ah, k5Al, k5Ah, k6Al, k6Ah;
    float k1Bl, k1Bh, k2Bl, k2Bh, k3Bl, k3Bh, k4Bl, k4Bh, k5Bl, k5Bh, k6Bl, k6Bh;

#pragma unroll 1
    for (int t = 0; t < NSTEPS; t++) {
        reinterpret_cast<float2*>(zs + ((size_t)bA * kT + t) * kH)[lane] = make_float2(zA0, zA1);
        reinterpret_cast<float2*>(zs + ((size_t)bB * kT + t) * kH)[lane] = make_float2(zB0, zB1);

        setu2(zA0, zA1, zB0, zB1);
        mlp2(k1Al, k1Ah, k1Bl, k1Bh);

        setu2(fmaf(dA21, k1Al, zA0), fmaf(dA21, k1Ah, zA1),
              fmaf(dA21, k1Bl, zB0), fmaf(dA21, k1Bh, zB1));
        mlp2(k2Al, k2Ah, k2Bl, k2Bh);

        {
            float uAl = fmaf(dA31, k1Al, zA0); uAl = fmaf(dA32, k2Al, uAl);
            float uAh = fmaf(dA31, k1Ah, zA1); uAh = fmaf(dA32, k2Ah, uAh);
            float uBl = fmaf(dA31, k1Bl, zB0); uBl = fmaf(dA32, k2Bl, uBl);
            float uBh = fmaf(dA31, k1Bh, zB1); uBh = fmaf(dA32, k2Bh, uBh);
            setu2(uAl, uAh, uBl, uBh);
        }
        mlp2(k3Al, k3Ah, k3Bl, k3Bh);

        {
            float uAl = fmaf(dA41, k1Al, zA0); uAl = fmaf(dA42, k2Al, uAl); uAl = fmaf(dA43, k3Al, uAl);
            float uAh = fmaf(dA41, k1Ah, zA1); uAh = fmaf(dA42, k2Ah, uAh); uAh = fmaf(dA43, k3Ah, uAh);
            float uBl = fmaf(dA41, k1Bl, zB0); uBl = fmaf(dA42, k2Bl, uBl); uBl = fmaf(dA43, k3Bl, uBl);
            float uBh = fmaf(dA41, k1Bh, zB1); uBh = fmaf(dA42, k2Bh, uBh); uBh = fmaf(dA43, k3Bh, uBh);
            setu2(uAl, uAh, uBl, uBh);
        }
        mlp2(k4Al, k4Ah, k4Bl, k4Bh);

        {
            float uAl = fmaf(dA51, k1Al, zA0); uAl = fmaf(dA52, k2Al, uAl);
            uAl = fmaf(dA53, k3Al, uAl); uAl = fmaf(dA54, k4Al, uAl);
            float uAh = fmaf(dA51, k1Ah, zA1); uAh = fmaf(dA52, k2Ah, uAh);
            uAh = fmaf(dA53, k3Ah, uAh); uAh = fmaf(dA54, k4Ah, uAh);
            float uBl = fmaf(dA51, k1Bl, zB0); uBl = fmaf(dA52, k2Bl, uBl);
            uBl = fmaf(dA53, k3Bl, uBl); uBl = fmaf(dA54, k4Bl, uBl);
            float uBh = fmaf(dA51, k1Bh, zB1); uBh = fmaf(dA52, k2Bh, uBh);
            uBh = fmaf(dA53, k3Bh, uBh); uBh = fmaf(dA54, k4Bh, uBh);
            setu2(uAl, uAh, uBl, uBh);
        }
        mlp2(k5Al, k5Ah, k5Bl, k5Bh);

        {
            float uAl = fmaf(dA61, k1Al, zA0); uAl = fmaf(dA62, k2Al, uAl);
            uAl = fmaf(dA63, k3Al, uAl); uAl = fmaf(dA64, k4Al, uAl); uAl = fmaf(dA65, k5Al, uAl);
            float uAh = fmaf(dA61, k1Ah, zA1); uAh = fmaf(dA62, k2Ah, uAh);
            uAh = fmaf(dA63, k3Ah, uAh); uAh = fmaf(dA64, k4Ah, uAh); uAh = fmaf(dA65, k5Ah, uAh);
            float uBl = fmaf(dA61, k1Bl, zB0); uBl = fmaf(dA62, k2Bl, uBl);
            uBl = fmaf(dA63, k3Bl, uBl); uBl = fmaf(dA64, k4Bl, uBl); uBl = fmaf(dA65, k5Bl, uBl);
            float uBh = fmaf(dA61, k1Bh, zB1); uBh = fmaf(dA62, k2Bh, uBh);
            uBh = fmaf(dA63, k3Bh, uBh); uBh = fmaf(dA64, k4Bh, uBh); uBh = fmaf(dA65, k5Bh, uBh);
            setu2(uAl, uAh, uBl, uBh);
        }
        mlp2(k6Al, k6Ah, k6Bl, k6Bh);

        {
            zA0 = fmaf(dB1, k1Al, zA0); zA0 = fmaf(dB2, k2Al, zA0); zA0 = fmaf(dB3, k3Al, zA0);
            zA0 = fmaf(dB4, k4Al, zA0); zA0 = fmaf(dB5, k5Al, zA0); zA0 = fmaf(dB6, k6Al, zA0);
            zA1 = fmaf(dB1, k1Ah, zA1); zA1 = fmaf(dB2, k2Ah, zA1); zA1 = fmaf(dB3, k3Ah, zA1);
            zA1 = fmaf(dB4, k4Ah, zA1); zA1 = fmaf(dB5, k5Ah, zA1); zA1 = fmaf(dB6, k6Ah, zA1);
            zB0 = fmaf(dB1, k1Bl, zB0); zB0 = fmaf(dB2, k2Bl, zB0); zB0 = fmaf(dB3, k3Bl, zB0);
            zB0 = fmaf(dB4, k4Bl, zB0); zB0 = fmaf(dB5, k5Bl, zB0); zB0 = fmaf(dB6, k6Bl, zB0);
            zB1 = fmaf(dB1, k1Bh, zB1); zB1 = fmaf(dB2, k2Bh, zB1); zB1 = fmaf(dB3, k3Bh, zB1);
            zB1 = fmaf(dB4, k4Bh, zB1); zB1 = fmaf(dB5, k5Bh, zB1); zB1 = fmaf(dB6, k6Bh, zB1);
        }
    }
    reinterpret_cast<float2*>(zs + ((size_t)bA * kT + NSTEPS) * kH)[lane] = make_float2(zA0, zA1);
    reinterpret_cast<float2*>(zs + ((size_t)bB * kT + NSTEPS) * kH)[lane] = make_float2(zB0, zB1);
}

// ---- decode: exact R11 cp.async depth-2 pipeline (measured best 92.1us) ----
constexpr int DEC_THREADS = 128;
constexpr int DEC_TILE = 16;
constexpr int DEC_GRID = 444;

__global__ void __launch_bounds__(DEC_THREADS)
dec_kernel(const float* __restrict__ zs, const float* __restrict__ decW,
           const float* __restrict__ decb, float* __restrict__ ys)
{
    __shared__ __align__(16) float sz[2][DEC_TILE * 64];
    const int tid = threadIdx.x;
    const int lane = tid & 31;
    const int wid = tid >> 5;

    u64 wa[32], wb[32];
    {
        const ulonglong2* va = reinterpret_cast<const ulonglong2*>(decW + (2*lane) * 64);
        const ulonglong2* vb = reinterpret_cast<const ulonglong2*>(decW + (2*lane+1) * 64);
#pragma unroll
        for (int i = 0; i < 16; i++) {
            ulonglong2 x = va[i], y = vb[i];
            wa[2*i] = x.x; wa[2*i+1] = x.y;
            wb[2*i] = y.x; wb[2*i+1] = y.y;
        }
    }
    const float2 db = *reinterpret_cast<const float2*>(decb + 2 * lane);

    const unsigned s0 = smem_u32(sz[0]);
    const unsigned s1 = smem_u32(sz[1]);
    const int nTiles = (kB * kT) / DEC_TILE;   // 25856

    int tile = blockIdx.x;
    if (tile < nTiles) {
        const char* g = reinterpret_cast<const char*>(zs + (size_t)tile * DEC_TILE * 64);
        cp_async16(s0 + tid * 16, g + tid * 16);
        cp_async16(s0 + (tid + 128) * 16, g + (tid + 128) * 16);
    }
    asm volatile("cp.async.commit_group;" ::: "memory");

    int buf = 0;
#pragma unroll 1
    for (; tile < nTiles; tile += DEC_GRID, buf ^= 1) {
        const int nt = tile + DEC_GRID;
        const unsigned snext = buf ? s0 : s1;
        if (nt < nTiles) {
            const char* g = reinterpret_cast<const char*>(zs + (size_t)nt * DEC_TILE * 64);
            cp_async16(snext + tid * 16, g + tid * 16);
            cp_async16(snext + (tid + 128) * 16, g + (tid + 128) * 16);
        }
        asm volatile("cp.async.commit_group;" ::: "memory");
        asm volatile("cp.async.wait_group 1;" ::: "memory");
        __syncthreads();

        const float* sb = sz[buf];
        const int r0 = wid * 4;
#pragma unroll
        for (int rr = 0; rr < 4; rr++) {
            const ulonglong2* zr = reinterpret_cast<const ulonglong2*>(sb + (r0 + rr) * 64);
            u64 a0 = pk(db.x, 0.f), a1 = 0, c0 = pk(db.y, 0.f), c1 = 0;
#pragma unroll
            for (int kc = 0; kc < 16; kc++) {
                ulonglong2 v = zr[kc];
                a0 = fma2(v.x, wa[2*kc], a0); a1 = fma2(v.y, wa[2*kc+1], a1);
                c0 = fma2(v.x, wb[2*kc], c0); c1 = fma2(v.y, wb[2*kc+1], c1);
            }
            const size_t row = (size_t)tile * DEC_TILE + r0 + rr;
            reinterpret_cast<float2*>(ys + row * 64)[lane] =
                make_float2(hsum2(a0, a1), hsum2(c0, c1));
        }
        __syncthreads();
    }
}

} // namespace

extern "C" void kernel_launch(void* const* d_in, const int* in_sizes, int n_in,
                              void* d_out, int out_size) {
    const float* ts   = (const float*)d_in[0];
    const float* y0   = (const float*)d_in[1];
    const float* encW = (const float*)d_in[2];
    const float* encb = (const float*)d_in[3];
    const float* W1   = (const float*)d_in[4];
    const float* b1   = (const float*)d_in[5];
    const float* W2   = (const float*)d_in[6];
    const float* b2   = (const float*)d_in[7];
    const float* W3   = (const float*)d_in[8];
    const float* b3   = (const float*)d_in[9];
    const float* decW = (const float*)d_in[10];
    const float* decb = (const float*)d_in[11];

    float* ys = (float*)d_out;
    float* zs = ys + (size_t)out_size / 2;     // [ys | zs]

    ode_kernel<<<GRID, THREADS>>>(ts, y0, encW, encb, W1, b1, W2, b2, W3, b3, zs);
    dec_kernel<<<DEC_GRID, DEC_THREADS>>>(zs, decW, decb, ys);
}

// round 14
// speedup vs baseline: 1.0181x; 1.0181x over previous
#include <cuda_runtime.h>
#include <math.h>

// NeuralODE on GB300, round 14 — recombination of measured bests.
// ode_kernel: byte-exact R12 (immediate-form Tsit5 combos + MUFU.TANH;
//   measured ~766us). R13's dt*coef precompute REGRESSED (+15us via register
//   pressure) and is reverted.
// dec_kernel: byte-exact R11 cp.async depth-2 pipeline (measured 92.1us).

namespace {

constexpr int kB = 4096;
constexpr int kT = 101;
constexpr int kH = 64;
constexpr int NSTEPS = kT - 1;

constexpr int NB = 2;
constexpr int WARPS = 4;
constexpr int THREADS = WARPS * 32;
constexpr int ELEMS_PER_BLOCK = WARPS * NB;  // 8
constexpr int GRID = kB / ELEMS_PER_BLOCK;   // 512

constexpr float A21 = 0.161f;
constexpr float A31 = -0.008480655492356989f, A32 = 0.335480655492357f;
constexpr float A41 = 2.8971530571054935f, A42 = -6.359448489975075f, A43 = 4.3622954328695815f;
constexpr float A51 = 5.325864828439257f, A52 = -11.748883564062828f;
constexpr float A53 = 7.4955393428898365f, A54 = -0.09249506636175525f;
constexpr float A61 = 5.86145544294642f, A62 = -12.92096931784711f;
constexpr float A63 = 8.159367898576159f, A64 = -0.071584973281401f, A65 = -0.028269050394068383f;
constexpr float B1c = 0.09646076681806523f, B2c = 0.01f, B3c = 0.4798896504144996f;
constexpr float B4c = 1.379008574103742f, B5c = -3.290069515436081f, B6c = 2.324710524099774f;

using u64 = unsigned long long;

__device__ __forceinline__ u64 pk(float x, float y) {
    u64 r; asm("mov.b64 %0, {%1,%2};" : "=l"(r) : "f"(x), "f"(y)); return r;
}
__device__ __forceinline__ u64 fma2(u64 a, u64 b, u64 c) {
    u64 d; asm("fma.rn.f32x2 %0, %1, %2, %3;" : "=l"(d) : "l"(a), "l"(b), "l"(c)); return d;
}
__device__ __forceinline__ float hsum2(u64 a, u64 b) {
    u64 s; asm("add.rn.f32x2 %0, %1, %2;" : "=l"(s) : "l"(a), "l"(b));
    float x, y;
    asm("mov.b64 {%0,%1}, %2;" : "=f"(x), "=f"(y) : "l"(s));
    return x + y;
}
__device__ __forceinline__ float tanh_f(float x) {
    // MUFU.TANH (validated: rel_err ~2.3e-6 vs 1e-3 gate)
    float r; asm("tanh.approx.f32 %0, %1;" : "=f"(r) : "f"(x));
    return r;
}
__device__ __forceinline__ unsigned smem_u32(const void* p) {
    unsigned a;
    asm("{ .reg .u64 t; cvta.to.shared.u64 t, %1; cvt.u32.u64 %0, t; }"
        : "=r"(a) : "l"(p));
    return a;
}
__device__ __forceinline__ void cp_async16(unsigned saddr, const void* gptr) {
    asm volatile("cp.async.cg.shared.global [%0], [%1], 16;"
                 :: "r"(saddr), "l"(gptr) : "memory");
}

__global__ void __launch_bounds__(THREADS, 2)
ode_kernel(
    const float* __restrict__ ts, const float* __restrict__ y0,
    const float* __restrict__ encW, const float* __restrict__ encb,
    const float* __restrict__ W1g, const float* __restrict__ b1g,
    const float* __restrict__ W2g, const float* __restrict__ b2g,
    const float* __restrict__ W3g, const float* __restrict__ b3g,
    float* __restrict__ zs)
{
    // per warp: suA[64] suB[64] sh1A[32] sh1B[32] sh2A[32] sh2B[32]
    __shared__ __align__(16) float sm[WARPS * 256];
    const int lane = threadIdx.x & 31;
    const int wid = threadIdx.x >> 5;
    float* suA  = sm + wid * 256;
    float* suB  = suA + 64;
    float* sh1A = suA + 128;
    float* sh1B = suA + 160;
    float* sh2A = suA + 192;
    float* sh2B = suA + 224;
    const int bA = blockIdx.x * ELEMS_PER_BLOCK + wid * NB;
    const int bB = bA + 1;

    // ---- register-resident MLP weights, K-packed ----
    u64 w1p[32];   // W1[lane][0..63]
    u64 w2p[16];   // W2[lane][0..31]
    u64 w3a[16];   // W3[2*lane][0..31]
    u64 w3b[16];   // W3[2*lane+1][0..31]
    {
        const ulonglong2* v1 = reinterpret_cast<const ulonglong2*>(W1g + lane * 64);
#pragma unroll
        for (int i = 0; i < 16; i++) { ulonglong2 v = v1[i]; w1p[2*i] = v.x; w1p[2*i+1] = v.y; }
        const ulonglong2* v2 = reinterpret_cast<const ulonglong2*>(W2g + lane * 32);
#pragma unroll
        for (int i = 0; i < 8; i++) { ulonglong2 v = v2[i]; w2p[2*i] = v.x; w2p[2*i+1] = v.y; }
        const ulonglong2* v3a = reinterpret_cast<const ulonglong2*>(W3g + (2*lane) * 32);
        const ulonglong2* v3b = reinterpret_cast<const ulonglong2*>(W3g + (2*lane+1) * 32);
#pragma unroll
        for (int i = 0; i < 8; i++) {
            ulonglong2 a = v3a[i], b = v3b[i];
            w3a[2*i] = a.x; w3a[2*i+1] = a.y;
            w3b[2*i] = b.x; w3b[2*i+1] = b.y;
        }
    }
    const float b1r = b1g[lane];
    const float b2r = b2g[lane];
    const float2 b3p = *reinterpret_cast<const float2*>(b3g + 2 * lane);
    const float dt = (ts[kT - 1] - ts[0]) / (float)NSTEPS;

    // ---- encoder for both elements ----
    float zA0, zA1, zB0, zB1;
    {
        reinterpret_cast<float2*>(suA)[lane] =
            *reinterpret_cast<const float2*>(y0 + (size_t)bA * 64 + 2 * lane);
        reinterpret_cast<float2*>(suB)[lane] =
            *reinterpret_cast<const float2*>(y0 + (size_t)bB * 64 + 2 * lane);
        __syncwarp();
        const ulonglong2* Ea = reinterpret_cast<const ulonglong2*>(encW + (2*lane) * 64);
        const ulonglong2* Eb = reinterpret_cast<const ulonglong2*>(encW + (2*lane+1) * 64);
        const float2 eb = *reinterpret_cast<const float2*>(encb + 2 * lane);
        u64 aA0 = pk(eb.x, 0.f), aA1 = 0, cA0 = pk(eb.y, 0.f), cA1 = 0;
        u64 aB0 = pk(eb.x, 0.f), aB1 = 0, cB0 = pk(eb.y, 0.f), cB1 = 0;
        const ulonglong2* uA = reinterpret_cast<const ulonglong2*>(suA);
        const ulonglong2* uB = reinterpret_cast<const ulonglong2*>(suB);
#pragma unroll
        for (int kc = 0; kc < 16; kc++) {
            ulonglong2 wA = Ea[kc], wB = Eb[kc];
            ulonglong2 vA = uA[kc], vB = uB[kc];
            aA0 = fma2(vA.x, wA.x, aA0); aA1 = fma2(vA.y, wA.y, aA1);
            cA0 = fma2(vA.x, wB.x, cA0); cA1 = fma2(vA.y, wB.y, cA1);
            aB0 = fma2(vB.x, wA.x, aB0); aB1 = fma2(vB.y, wA.y, aB1);
            cB0 = fma2(vB.x, wB.x, cB0); cB1 = fma2(vB.y, wB.y, cB1);
        }
        zA0 = hsum2(aA0, aA1); zA1 = hsum2(cA0, cA1);
        zB0 = hsum2(aB0, aB1); zB1 = hsum2(cB0, cB1);
        __syncwarp();
    }

    // MLP field eval for both elements; input in suA/suB.
    auto mlp2 = [&](float& oAl, float& oAh, float& oBl, float& oBh) {
        // layer 1: 64 -> 32, tanh
        u64 aA0 = pk(b1r, 0.f), aA1 = 0, aB0 = pk(b1r, 0.f), aB1 = 0;
        {
            const ulonglong2* uA = reinterpret_cast<const ulonglong2*>(suA);
            const ulonglong2* uB = reinterpret_cast<const ulonglong2*>(suB);
#pragma unroll
            for (int kc = 0; kc < 16; kc++) {
                ulonglong2 vA = uA[kc], vB = uB[kc];
                aA0 = fma2(vA.x, w1p[2*kc], aA0); aA1 = fma2(vA.y, w1p[2*kc+1], aA1);
                aB0 = fma2(vB.x, w1p[2*kc], aB0); aB1 = fma2(vB.y, w1p[2*kc+1], aB1);
            }
        }
        sh1A[lane] = tanh_f(hsum2(aA0, aA1));
        sh1B[lane] = tanh_f(hsum2(aB0, aB1));
        __syncwarp();
        // layer 2: 32 -> 32, tanh
        u64 cA0 = pk(b2r, 0.f), cA1 = 0, cB0 = pk(b2r, 0.f), cB1 = 0;
        {
            const ulonglong2* hA = reinterpret_cast<const ulonglong2*>(sh1A);
            const ulonglong2* hB = reinterpret_cast<const ulonglong2*>(sh1B);
#pragma unroll
            for (int kc = 0; kc < 8; kc++) {
                ulonglong2 vA = hA[kc], vB = hB[kc];
                cA0 = fma2(vA.x, w2p[2*kc], cA0); cA1 = fma2(vA.y, w2p[2*kc+1], cA1);
                cB0 = fma2(vB.x, w2p[2*kc], cB0); cB1 = fma2(vB.y, w2p[2*kc+1], cB1);
            }
        }
        sh2A[lane] = tanh_f(hsum2(cA0, cA1));
        sh2B[lane] = tanh_f(hsum2(cB0, cB1));
        __syncwarp();
        // layer 3: 32 -> 64 (lane outputs comps 2*lane, 2*lane+1)
        u64 dA0 = pk(b3p.x, 0.f), dA1 = 0, eA0 = pk(b3p.y, 0.f), eA1 = 0;
        u64 dB0 = pk(b3p.x, 0.f), dB1 = 0, eB0 = pk(b3p.y, 0.f), eB1 = 0;
        {
            const ulonglong2* hA = reinterpret_cast<const ulonglong2*>(sh2A);
            const ulonglong2* hB = reinterpret_cast<const ulonglong2*>(sh2B);
#pragma unroll
            for (int kc = 0; kc < 8; kc++) {
                ulonglong2 vA = hA[kc], vB = hB[kc];
                dA0 = fma2(vA.x, w3a[2*kc], dA0); dA1 = fma2(vA.y, w3a[2*kc+1], dA1);
                eA0 = fma2(vA.x, w3b[2*kc], eA0); eA1 = fma2(vA.y, w3b[2*kc+1], eA1);
                dB0 = fma2(vB.x, w3a[2*kc], dB0); dB1 = fma2(vB.y, w3a[2*kc+1], dB1);
                eB0 = fma2(vB.x, w3b[2*kc], eB0); eB1 = fma2(vB.y, w3b[2*kc+1], eB1);
            }
        }
        oAl = hsum2(dA0, dA1); oAh = hsum2(eA0, eA1);
        oBl = hsum2(dB0, dB1); oBh = hsum2(eB0, eB1);
    };

    auto setu2 = [&](float uAl, float uAh, float uBl, float uBh) {
        reinterpret_cast<float2*>(suA)[lane] = make_float2(uAl, uAh);
        reinterpret_cast<float2*>(suB)[lane] = make_float2(uBl, uBh);
        __syncwarp();
    };

    float k1Al, k1Ah, k2Al, k2Ah, k3Al, k3Ah, k4Al, k4Ah, k5Al, k5Ah, k6Al, k6Ah;
    float k1Bl, k1Bh, k2Bl, k2Bh, k3Bl, k3Bh, k4Bl, k4Bh, k5Bl, k5Bh, k6Bl, k6Bh;

#pragma unroll 1
    for (int t = 0; t < NSTEPS; t++) {
        reinterpret_cast<float2*>(zs + ((size_t)bA * kT + t) * kH)[lane] = make_float2(zA0, zA1);
        reinterpret_cast<float2*>(zs + ((size_t)bB * kT + t) * kH)[lane] = make_float2(zB0, zB1);

        setu2(zA0, zA1, zB0, zB1);
        mlp2(k1Al, k1Ah, k1Bl, k1Bh);

        setu2(fmaf(dt, A21 * k1Al, zA0), fmaf(dt, A21 * k1Ah, zA1),
              fmaf(dt, A21 * k1Bl, zB0), fmaf(dt, A21 * k1Bh, zB1));
        mlp2(k2Al, k2Ah, k2Bl, k2Bh);

        {
            float aAl = fmaf(A32, k2Al, A31 * k1Al), aAh = fmaf(A32, k2Ah, A31 * k1Ah);
            float aBl = fmaf(A32, k2Bl, A31 * k1Bl), aBh = fmaf(A32, k2Bh, A31 * k1Bh);
            setu2(fmaf(dt, aAl, zA0), fmaf(dt, aAh, zA1),
                  fmaf(dt, aBl, zB0), fmaf(dt, aBh, zB1));
        }
        mlp2(k3Al, k3Ah, k3Bl, k3Bh);

        {
            float aAl = fmaf(A42, k2Al, A41 * k1Al); aAl = fmaf(A43, k3Al, aAl);
            float aAh = fmaf(A42, k2Ah, A41 * k1Ah); aAh = fmaf(A43, k3Ah, aAh);
            float aBl = fmaf(A42, k2Bl, A41 * k1Bl); aBl = fmaf(A43, k3Bl, aBl);
            float aBh = fmaf(A42, k2Bh, A41 * k1Bh); aBh = fmaf(A43, k3Bh, aBh);
            setu2(fmaf(dt, aAl, zA0), fmaf(dt, aAh, zA1),
                  fmaf(dt, aBl, zB0), fmaf(dt, aBh, zB1));
        }
        mlp2(k4Al, k4Ah, k4Bl, k4Bh);

        {
            float aAl = fmaf(A52, k2Al, A51 * k1Al); aAl = fmaf(A53, k3Al, aAl); aAl = fmaf(A54, k4Al, aAl);
            float aAh = fmaf(A52, k2Ah, A51 * k1Ah); aAh = fmaf(A53, k3Ah, aAh); aAh = fmaf(A54, k4Ah, aAh);
            float aBl = fmaf(A52, k2Bl, A51 * k1Bl); aBl = fmaf(A53, k3Bl, aBl); aBl = fmaf(A54, k4Bl, aBl);
            float aBh = fmaf(A52, k2Bh, A51 * k1Bh); aBh = fmaf(A53, k3Bh, aBh); aBh = fmaf(A54, k4Bh, aBh);
            setu2(fmaf(dt, aAl, zA0), fmaf(dt, aAh, zA1),
                  fmaf(dt, aBl, zB0), fmaf(dt, aBh, zB1));
        }
        mlp2(k5Al, k5Ah, k5Bl, k5Bh);

        {
            float aAl = fmaf(A62, k2Al, A61 * k1Al); aAl = fmaf(A63, k3Al, aAl);
            aAl = fmaf(A64, k4Al, aAl); aAl = fmaf(A65, k5Al, aAl);
            float aAh = fmaf(A62, k2Ah, A61 * k1Ah); aAh = fmaf(A63, k3Ah, aAh);
            aAh = fmaf(A64, k4Ah, aAh); aAh = fmaf(A65, k5Ah, aAh);
            float aBl = fmaf(A62, k2Bl, A61 * k1Bl); aBl = fmaf(A63, k3Bl, aBl);
            aBl = fmaf(A64, k4Bl, aBl); aBl = fmaf(A65, k5Bl, aBl);
            float aBh = fmaf(A62, k2Bh, A61 * k1Bh); aBh = fmaf(A63, k3Bh, aBh);
            aBh = fmaf(A64, k4Bh, aBh); aBh = fmaf(A65, k5Bh, aBh);
            setu2(fmaf(dt, aAl, zA0), fmaf(dt, aAh, zA1),
                  fmaf(dt, aBl, zB0), fmaf(dt, aBh, zB1));
        }
        mlp2(k6Al, k6Ah, k6Bl, k6Bh);

        {
            float s;
            s = B1c * k1Al; s = fmaf(B2c, k2Al, s); s = fmaf(B3c, k3Al, s);
            s = fmaf(B4c, k4Al, s); s = fmaf(B5c, k5Al, s); s = fmaf(B6c, k6Al, s);
            zA0 = fmaf(dt, s, zA0);
            s = B1c * k1Ah; s = fmaf(B2c, k2Ah, s); s = fmaf(B3c, k3Ah, s);
            s = fmaf(B4c, k4Ah, s); s = fmaf(B5c, k5Ah, s); s = fmaf(B6c, k6Ah, s);
            zA1 = fmaf(dt, s, zA1);
            s = B1c * k1Bl; s = fmaf(B2c, k2Bl, s); s = fmaf(B3c, k3Bl, s);
            s = fmaf(B4c, k4Bl, s); s = fmaf(B5c, k5Bl, s); s = fmaf(B6c, k6Bl, s);
            zB0 = fmaf(dt, s, zB0);
            s = B1c * k1Bh; s = fmaf(B2c, k2Bh, s); s = fmaf(B3c, k3Bh, s);
            s = fmaf(B4c, k4Bh, s); s = fmaf(B5c, k5Bh, s); s = fmaf(B6c, k6Bh, s);
            zB1 = fmaf(dt, s, zB1);
        }
    }
    reinterpret_cast<float2*>(zs + ((size_t)bA * kT + NSTEPS) * kH)[lane] = make_float2(zA0, zA1);
    reinterpret_cast<float2*>(zs + ((size_t)bB * kT + NSTEPS) * kH)[lane] = make_float2(zB0, zB1);
}

// ---- decode: exact R11 cp.async depth-2 pipeline (measured best 92.1us) ----
constexpr int DEC_THREADS = 128;
constexpr int DEC_TILE = 16;
constexpr int DEC_GRID = 444;

__global__ void __launch_bounds__(DEC_THREADS)
dec_kernel(const float* __restrict__ zs, const float* __restrict__ decW,
           const float* __restrict__ decb, float* __restrict__ ys)
{
    __shared__ __align__(16) float sz[2][DEC_TILE * 64];
    const int tid = threadIdx.x;
    const int lane = tid & 31;
    const int wid = tid >> 5;

    u64 wa[32], wb[32];
    {
        const ulonglong2* va = reinterpret_cast<const ulonglong2*>(decW + (2*lane) * 64);
        const ulonglong2* vb = reinterpret_cast<const ulonglong2*>(decW + (2*lane+1) * 64);
#pragma unroll
        for (int i = 0; i < 16; i++) {
            ulonglong2 x = va[i], y = vb[i];
            wa[2*i] = x.x; wa[2*i+1] = x.y;
            wb[2*i] = y.x; wb[2*i+1] = y.y;
        }
    }
    const float2 db = *reinterpret_cast<const float2*>(decb + 2 * lane);

    const unsigned s0 = smem_u32(sz[0]);
    const unsigned s1 = smem_u32(sz[1]);
    const int nTiles = (kB * kT) / DEC_TILE;   // 25856

    int tile = blockIdx.x;
    if (tile < nTiles) {
        const char* g = reinterpret_cast<const char*>(zs + (size_t)tile * DEC_TILE * 64);
        cp_async16(s0 + tid * 16, g + tid * 16);
        cp_async16(s0 + (tid + 128) * 16, g + (tid + 128) * 16);
    }
    asm volatile("cp.async.commit_group;" ::: "memory");

    int buf = 0;
#pragma unroll 1
    for (; tile < nTiles; tile += DEC_GRID, buf ^= 1) {
        const int nt = tile + DEC_GRID;
        const unsigned snext = buf ? s0 : s1;
        if (nt < nTiles) {
            const char* g = reinterpret_cast<const char*>(zs + (size_t)nt * DEC_TILE * 64);
            cp_async16(snext + tid * 16, g + tid * 16);
            cp_async16(snext + (tid + 128) * 16, g + (tid + 128) * 16);
        }
        asm volatile("cp.async.commit_group;" ::: "memory");
        asm volatile("cp.async.wait_group 1;" ::: "memory");
        __syncthreads();

        const float* sb = sz[buf];
        const int r0 = wid * 4;
#pragma unroll
        for (int rr = 0; rr < 4; rr++) {
            const ulonglong2* zr = reinterpret_cast<const ulonglong2*>(sb + (r0 + rr) * 64);
            u64 a0 = pk(db.x, 0.f), a1 = 0, c0 = pk(db.y, 0.f), c1 = 0;
#pragma unroll
            for (int kc = 0; kc < 16; kc++) {
                ulonglong2 v = zr[kc];
                a0 = fma2(v.x, wa[2*kc], a0); a1 = fma2(v.y, wa[2*kc+1], a1);
                c0 = fma2(v.x, wb[2*kc], c0); c1 = fma2(v.y, wb[2*kc+1], c1);
            }
            const size_t row = (size_t)tile * DEC_TILE + r0 + rr;
            reinterpret_cast<float2*>(ys + row * 64)[lane] =
                make_float2(hsum2(a0, a1), hsum2(c0, c1));
        }
        __syncthreads();
    }
}

} // namespace

extern "C" void kernel_launch(void* const* d_in, const int* in_sizes, int n_in,
                              void* d_out, int out_size) {
    const float* ts   = (const float*)d_in[0];
    const float* y0   = (const float*)d_in[1];
    const float* encW = (const float*)d_in[2];
    const float* encb = (const float*)d_in[3];
    const float* W1   = (const float*)d_in[4];
    const float* b1   = (const float*)d_in[5];
    const float* W2   = (const float*)d_in[6];
    const float* b2   = (const float*)d_in[7];
    const float* W3   = (const float*)d_in[8];
    const float* b3   = (const float*)d_in[9];
    const float* decW = (const float*)d_in[10];
    const float* decb = (const float*)d_in[11];

    float* ys = (float*)d_out;
    float* zs = ys + (size_t)out_size / 2;     // [ys | zs]

    ode_kernel<<<GRID, THREADS>>>(ts, y0, encW, encb, W1, b1, W2, b2, W3, b3, zs);
    dec_kernel<<<DEC_GRID, DEC_THREADS>>>(zs, decW, decb, ys);
}